// round 5
// baseline (speedup 1.0000x reference)
#include <cuda_runtime.h>
#include <cuda_bf16.h>
#include <cstdint>
#include <math.h>

#define NTOT 65536
#define BG   64
#define NPG  1024
#define ETOT 1048576
#define EPG  (ETOT / BG)     // 16384 edges per graph (edge e -> graph e/EPG)
#define DD   128
#define KK   512             // NPG/2

// ---------------- scratch (device globals: allocation-free) ----------------
__device__ float g_h[(size_t)NTOT * DD];      // agg = A_hat @ x
__device__ float g_o[(size_t)NTOT * DD];      // relu(conv output)
__device__ float g_dinv[NTOT];
__device__ float g_score[NTOT];
__device__ float g_pinv;
__device__ int   g_off[NTOT + 1];             // global CSR offsets (by dst)
__device__ int2  g_epack[ETOT];               // {src_local, norm bits} grouped by dst

// ========== fused per-graph CSR build: deg + dinv + count + scan + fill ==========
__global__ __launch_bounds__(512) void k_build(const int* __restrict__ ei,
                                               const float* __restrict__ ew) {
    __shared__ float sdeg[NPG];     // deg -> dinv in place
    __shared__ int   scnt[NPG];
    __shared__ int   soff[NPG];
    __shared__ int   scur[NPG];
    __shared__ int   s2[512];

    int g = blockIdx.x;
    int t = threadIdx.x;
    int base_e = g * EPG;
    int base_n = g * NPG;
    const int* src = ei;
    const int* dst = ei + ETOT;

    // init
    #pragma unroll
    for (int i = t; i < NPG; i += 512) { sdeg[i] = 1.0f; scnt[i] = 0; }
    __syncthreads();

    // pass 1: degree + counts (smem atomics)
    for (int e = t; e < EPG; e += 512) {
        int d = dst[base_e + e] - base_n;
        atomicAdd(&sdeg[d], ew[base_e + e]);
        atomicAdd(&scnt[d], 1);
    }
    __syncthreads();

    // dinv in place
    #pragma unroll
    for (int i = t; i < NPG; i += 512)
        sdeg[i] = rsqrtf(fmaxf(sdeg[i], 1e-12f));
    __syncthreads();

    // exclusive scan of scnt (pairs + Hillis-Steele over 512)
    int c0 = scnt[2 * t], c1 = scnt[2 * t + 1];
    int pairsum = c0 + c1;
    s2[t] = pairsum;
    __syncthreads();
    for (int d = 1; d < 512; d <<= 1) {
        int u = (t >= d) ? s2[t - d] : 0;
        __syncthreads(); s2[t] += u; __syncthreads();
    }
    int excl = s2[t] - pairsum;
    soff[2 * t]     = excl;
    soff[2 * t + 1] = excl + c0;
    scur[2 * t]     = excl;
    scur[2 * t + 1] = excl + c0;
    __syncthreads();

    // write global dinv + offsets
    #pragma unroll
    for (int i = t; i < NPG; i += 512) {
        g_dinv[base_n + i] = sdeg[i];
        g_off[base_n + i]  = base_e + soff[i];
    }
    if (g == 0 && t == 0) g_off[NTOT] = ETOT;

    // pass 2: fill epack with {src_local, norm}
    for (int e = t; e < EPG; e += 512) {
        int s = src[base_e + e] - base_n;
        int d = dst[base_e + e] - base_n;
        float nrm = sdeg[s] * ew[base_e + e] * sdeg[d];
        int pos = atomicAdd(&scur[d], 1);
        g_epack[base_e + pos] = make_int2(s, __float_as_int(nrm));
    }
}

// ---------------- p norm ----------------
__global__ void k_pnorm(const float* __restrict__ p) {
    int lane = threadIdx.x;
    float4 pv = ((const float4*)p)[lane];
    float pp = pv.x * pv.x + pv.y * pv.y + pv.z * pv.z + pv.w * pv.w;
    #pragma unroll
    for (int off = 16; off > 0; off >>= 1) pp += __shfl_xor_sync(0xFFFFFFFFu, pp, off);
    if (lane == 0) g_pinv = rsqrtf(pp);
}

// ========== smem-staged gather: agg = A_hat @ x, block = (graph, 32-col quarter) ==========
#define GSM_BYTES (NPG * 32 * 4)    // xs[1024][32] floats = 128 KB

__global__ __launch_bounds__(512, 1) void k_gather_sm(const float* __restrict__ x) {
    extern __shared__ float xs[];   // [1024][32], pitch 32 (conflict-free: lane==col)
    int g = blockIdx.x >> 2;
    int q = blockIdx.x & 3;
    int base_n = g * NPG;
    int base_e = g * EPG;
    int t = threadIdx.x;
    int w = t >> 5;
    int lane = t & 31;

    // stage x tile: rows base_n..+1024, cols q*32..+32
    for (int i = t; i < NPG * 8; i += 512) {
        int r = i >> 3, c4 = i & 7;
        float4 v = *(const float4*)&x[(size_t)(base_n + r) * DD + q * 32 + c4 * 4];
        float* dp = &xs[r * 32 + c4 * 4];
        dp[0] = v.x; dp[1] = v.y; dp[2] = v.z; dp[3] = v.w;
    }
    __syncthreads();

    // each warp handles nodes w, w+16, ... (64 nodes)
    for (int node = w; node < NPG; node += 16) {
        int gnode = base_n + node;
        float di = g_dinv[gnode];
        float acc = di * di * xs[node * 32 + lane];

        int i0 = g_off[gnode] - base_e;
        int i1 = g_off[gnode + 1] - base_e;
        for (int bb = i0; bb < i1; bb += 32) {
            int nload = i1 - bb; if (nload > 32) nload = 32;
            int2 pk = make_int2(0, 0);
            if (lane < nload) pk = g_epack[base_e + bb + lane];
            int j = 0;
            for (; j + 4 <= nload; j += 4) {
                #pragma unroll
                for (int u = 0; u < 4; u++) {
                    int   s  = __shfl_sync(0xFFFFFFFFu, pk.x, j + u);
                    float nm = __int_as_float(__shfl_sync(0xFFFFFFFFu, pk.y, j + u));
                    acc += nm * xs[s * 32 + lane];
                }
            }
            for (; j < nload; j++) {
                int   s  = __shfl_sync(0xFFFFFFFFu, pk.x, j);
                float nm = __int_as_float(__shfl_sync(0xFFFFFFFFu, pk.y, j));
                acc += nm * xs[s * 32 + lane];
            }
        }
        g_h[(size_t)gnode * DD + q * 32 + lane] = acc;
    }
}

// ========== tensor-core GEMM (mma.sync bf16-split): out = relu(agg@W + b), score ==========
#define AP 132
#define SM_A_HI 0
#define SM_A_LO (128 * AP)
#define SM_B_HI (2 * 128 * AP)
#define SM_B_LO (3 * 128 * AP)
#define SM_BF16_ELEMS (4 * 128 * AP)
#define SM_F_OFF (SM_BF16_ELEMS * 2)
#define GTC_SMEM (SM_F_OFF + 2 * DD * 4)

__device__ __forceinline__ void bf16_split(float v, __nv_bfloat16& hi, __nv_bfloat16& lo) {
    hi = __float2bfloat16_rn(v);
    lo = __float2bfloat16_rn(v - __bfloat162float(hi));
}

__device__ __forceinline__ void mma_bf16(float* c, uint32_t a0, uint32_t a1, uint32_t a2,
                                         uint32_t a3, uint32_t b0, uint32_t b1) {
    asm volatile(
        "mma.sync.aligned.m16n8k16.row.col.f32.bf16.bf16.f32 "
        "{%0,%1,%2,%3}, {%4,%5,%6,%7}, {%8,%9}, {%0,%1,%2,%3};"
        : "+f"(c[0]), "+f"(c[1]), "+f"(c[2]), "+f"(c[3])
        : "r"(a0), "r"(a1), "r"(a2), "r"(a3), "r"(b0), "r"(b1));
}

__global__ __launch_bounds__(256, 1) void k_gemm_mma(const float* __restrict__ W,
                                                     const float* __restrict__ bvec,
                                                     const float* __restrict__ pvec) {
    extern __shared__ __nv_bfloat16 smb[];
    __nv_bfloat16* Ah = smb + SM_A_HI;
    __nv_bfloat16* Al = smb + SM_A_LO;
    __nv_bfloat16* Bh = smb + SM_B_HI;
    __nv_bfloat16* Bl = smb + SM_B_LO;
    float* bs = (float*)((char*)smb + SM_F_OFF);
    float* ps = bs + DD;

    int tid = threadIdx.x;
    int rb  = blockIdx.x * 128;

    for (int i = tid; i < 128 * 32; i += 256) {
        int r = i >> 5, q = i & 31;
        float4 v = *(const float4*)&g_h[(size_t)(rb + r) * DD + q * 4];
        __nv_bfloat16 h0, l0, h1, l1, h2, l2, h3, l3;
        bf16_split(v.x, h0, l0); bf16_split(v.y, h1, l1);
        bf16_split(v.z, h2, l2); bf16_split(v.w, h3, l3);
        __nv_bfloat16* ah = &Ah[r * AP + q * 4];
        __nv_bfloat16* al = &Al[r * AP + q * 4];
        ah[0] = h0; ah[1] = h1; ah[2] = h2; ah[3] = h3;
        al[0] = l0; al[1] = l1; al[2] = l2; al[3] = l3;
    }
    for (int i = tid; i < 128 * 32; i += 256) {
        int k = i >> 5, q = i & 31;
        float4 v = *(const float4*)&W[(size_t)k * DD + q * 4];
        float vv[4] = {v.x, v.y, v.z, v.w};
        #pragma unroll
        for (int j = 0; j < 4; j++) {
            __nv_bfloat16 hi, lo;
            bf16_split(vv[j], hi, lo);
            Bh[(q * 4 + j) * AP + k] = hi;
            Bl[(q * 4 + j) * AP + k] = lo;
        }
    }
    if (tid < DD) { bs[tid] = bvec[tid]; ps[tid] = pvec[tid]; }
    __syncthreads();

    int w  = tid >> 5;
    int l  = tid & 31;
    int qr = l >> 2;
    int qc = l & 3;

    float acc[16][4];
    #pragma unroll
    for (int t = 0; t < 16; t++)
        #pragma unroll
        for (int j = 0; j < 4; j++) acc[t][j] = 0.0f;

    const __nv_bfloat16* arow0  = Ah + (w * 16 + qr) * AP;
    const __nv_bfloat16* arow1  = arow0 + 8 * AP;
    const __nv_bfloat16* alrow0 = Al + (w * 16 + qr) * AP;
    const __nv_bfloat16* alrow1 = alrow0 + 8 * AP;

    #pragma unroll
    for (int ks = 0; ks < 8; ks++) {
        int k0 = ks * 16;
        uint32_t ah0 = *(const uint32_t*)(arow0  + k0 + qc * 2);
        uint32_t ah1 = *(const uint32_t*)(arow1  + k0 + qc * 2);
        uint32_t ah2 = *(const uint32_t*)(arow0  + k0 + 8 + qc * 2);
        uint32_t ah3 = *(const uint32_t*)(arow1  + k0 + 8 + qc * 2);
        uint32_t al0 = *(const uint32_t*)(alrow0 + k0 + qc * 2);
        uint32_t al1 = *(const uint32_t*)(alrow1 + k0 + qc * 2);
        uint32_t al2 = *(const uint32_t*)(alrow0 + k0 + 8 + qc * 2);
        uint32_t al3 = *(const uint32_t*)(alrow1 + k0 + 8 + qc * 2);

        #pragma unroll
        for (int t = 0; t < 16; t++) {
            const __nv_bfloat16* brow  = Bh + (t * 8 + qr) * AP;
            const __nv_bfloat16* browl = Bl + (t * 8 + qr) * AP;
            uint32_t bh0 = *(const uint32_t*)(brow  + k0 + qc * 2);
            uint32_t bh1 = *(const uint32_t*)(brow  + k0 + 8 + qc * 2);
            uint32_t bl0 = *(const uint32_t*)(browl + k0 + qc * 2);
            uint32_t bl1 = *(const uint32_t*)(browl + k0 + 8 + qc * 2);
            mma_bf16(acc[t], ah0, ah1, ah2, ah3, bh0, bh1);
            mma_bf16(acc[t], ah0, ah1, ah2, ah3, bl0, bl1);
            mma_bf16(acc[t], al0, al1, al2, al3, bh0, bh1);
        }
    }

    int r0 = rb + w * 16 + qr;
    int r1 = r0 + 8;
    float s0 = 0.0f, s1 = 0.0f;
    #pragma unroll
    for (int t = 0; t < 16; t++) {
        int c0 = t * 8 + qc * 2;
        float b0 = bs[c0], b1 = bs[c0 + 1];
        float p0 = ps[c0], p1 = ps[c0 + 1];
        float v00 = fmaxf(acc[t][0] + b0, 0.0f);
        float v01 = fmaxf(acc[t][1] + b1, 0.0f);
        float v10 = fmaxf(acc[t][2] + b0, 0.0f);
        float v11 = fmaxf(acc[t][3] + b1, 0.0f);
        *(float2*)&g_o[(size_t)r0 * DD + c0] = make_float2(v00, v01);
        *(float2*)&g_o[(size_t)r1 * DD + c0] = make_float2(v10, v11);
        s0 += v00 * p0 + v01 * p1;
        s1 += v10 * p0 + v11 * p1;
    }
    s0 += __shfl_xor_sync(0xFFFFFFFFu, s0, 1);
    s0 += __shfl_xor_sync(0xFFFFFFFFu, s0, 2);
    s1 += __shfl_xor_sync(0xFFFFFFFFu, s1, 1);
    s1 += __shfl_xor_sync(0xFFFFFFFFu, s1, 2);
    if (qc == 0) {
        float pin = g_pinv;
        g_score[r0] = s0 * pin;
        g_score[r1] = s1 * pin;
    }
}

// ---------------- top-K threshold + weighted mean (order-invariant) ----------------
__global__ void k_pool(float* __restrict__ out) {
    __shared__ float s_sc[NPG];
    __shared__ float s_sort[NPG];
    __shared__ float s_w[NPG];
    __shared__ float s_part[8 * DD];
    __shared__ int   s_cnt;

    int g = blockIdx.x;
    int t = threadIdx.x;
    int base = g * NPG;

    float sc = g_score[base + t];
    s_sc[t] = sc; s_sort[t] = sc;
    if (t == 0) s_cnt = 0;
    __syncthreads();

    for (int k = 2; k <= NPG; k <<= 1) {
        for (int j = k >> 1; j > 0; j >>= 1) {
            int ixj = t ^ j;
            if (ixj > t) {
                float a = s_sort[t], b = s_sort[ixj];
                bool up = ((t & k) == 0);
                if ((a > b) == up) { s_sort[t] = b; s_sort[ixj] = a; }
            }
            __syncthreads();
        }
    }
    float thr = s_sort[NPG - KK];
    __syncthreads();

    int isgt = (sc > thr);
    if (isgt) atomicAdd(&s_cnt, 1);
    __syncthreads();
    int need_eq = KK - s_cnt;

    float wgt = 0.0f;
    if (isgt) {
        wgt = tanhf(sc);
    } else if (sc == thr) {
        int r = 0;
        for (int j = 0; j < t; j++) if (s_sc[j] == thr) r++;
        if (r < need_eq) wgt = tanhf(sc);
    }
    s_w[t] = wgt;
    __syncthreads();

    int grp = t >> 7, c = t & 127;
    float part = 0.0f;
    for (int n = grp; n < NPG; n += 8) {
        float wn = s_w[n];
        if (wn != 0.0f) part += wn * g_o[(size_t)(base + n) * DD + c];
    }
    s_part[grp * DD + c] = part;
    __syncthreads();

    if (t < DD) {
        float s = 0.0f;
        #pragma unroll
        for (int q = 0; q < 8; q++) s += s_part[q * DD + t];
        out[g * DD + t] = s * (1.0f / (float)KK);
    }
}

// ---------------- launch ----------------
extern "C" void kernel_launch(void* const* d_in, const int* in_sizes, int n_in,
                              void* d_out, int out_size) {
    const float* x  = (const float*)d_in[0];
    const float* ew = (const float*)d_in[1];
    const float* W  = (const float*)d_in[2];
    const float* b  = (const float*)d_in[3];
    const float* p  = (const float*)d_in[4];
    const int*   ei = (const int*)d_in[5];
    float* out = (float*)d_out;

    static int s_attr_done = 0;
    if (!s_attr_done) {
        cudaFuncSetAttribute(k_gemm_mma, cudaFuncAttributeMaxDynamicSharedMemorySize, GTC_SMEM);
        cudaFuncSetAttribute(k_gather_sm, cudaFuncAttributeMaxDynamicSharedMemorySize, GSM_BYTES);
        s_attr_done = 1;
    }

    k_build<<<BG, 512>>>(ei, ew);
    k_pnorm<<<1, 32>>>(p);
    k_gather_sm<<<BG * 4, 512, GSM_BYTES>>>(x);
    k_gemm_mma<<<NTOT / 128, 256, GTC_SMEM>>>(W, b, p);
    k_pool<<<BG, NPG>>>(out);
}